// round 6
// baseline (speedup 1.0000x reference)
#include <cuda_runtime.h>
#include <cuda_fp16.h>
#include <math.h>

// ---------------------------------------------------------------------------
// Persistent kernel, 296 blocks (2/SM), software grid barriers.
// Rank-2 attention: sigmoid(Q·K_k) = 0.5 + 0.5*tanh(A*xr0_k + B*xr1_k + C)
// tanh evaluated 2-at-a-time via tanh.approx.f16x2 (MUFU halved).
// ---------------------------------------------------------------------------
#define NBLK   296
#define NTHR   256
#define M_TOK  16384
#define TN     8192
#define NSLICE 37          // key slices per batch
#define SLICE_LEN 222      // 37*222 >= 8192

__device__ float  g_comp_part[128 * 16384];    // [chunk][b*256+p][oc]
__device__ float  g_comp[16384];               // [b][pix256][oc32]
__device__ float4 g_ABC[M_TOK];                // (A,B,C,·) per query
__device__ float2 g_XR[M_TOK];                 // xr per token
__device__ float2 g_xrsum[64];                 // per-block Σxr (blocks 0..63)
__device__ float4 g_att[NSLICE * M_TOK];       // (S0,S1,S2,·) partials
__device__ unsigned long long g_barc;          // barrier ticket counter

using u64 = unsigned long long;
__device__ __forceinline__ u64 pack2(float lo, float hi) {
    u64 r; asm("mov.b64 %0,{%1,%2};" : "=l"(r) : "f"(lo), "f"(hi)); return r;
}
__device__ __forceinline__ void unpack2(u64 v, float& lo, float& hi) {
    asm("mov.b64 {%0,%1},%2;" : "=f"(lo), "=f"(hi) : "l"(v));
}
__device__ __forceinline__ u64 fma2(u64 a, u64 b, u64 c) {
    u64 d; asm("fma.rn.f32x2 %0,%1,%2,%3;" : "=l"(d) : "l"(a), "l"(b), "l"(c)); return d;
}
__device__ __forceinline__ u64 add2(u64 a, u64 b) {
    u64 d; asm("add.rn.f32x2 %0,%1,%2;" : "=l"(d) : "l"(a), "l"(b)); return d;
}
// pack 2 f32 logits -> f16x2, tanh both in ONE MUFU op, return packed halves
__device__ __forceinline__ unsigned tanh2_f16(float l0, float l1) {
    unsigned h;
    asm("cvt.rn.f16x2.f32 %0,%1,%2;" : "=r"(h) : "f"(l1), "f"(l0)); // lo=l0, hi=l1
    asm("tanh.approx.f16x2 %0,%0;" : "+r"(h));
    return h;
}
__device__ __forceinline__ float sigf(float x) { return 1.f / (1.f + expf(-x)); }

__device__ __forceinline__ void gridbar() {
    __syncthreads();
    if (threadIdx.x == 0) {
        __threadfence();
        unsigned long long ticket = atomicAdd(&g_barc, 1ULL);
        unsigned long long target = (ticket / NBLK + 1ULL) * (unsigned long long)NBLK;
        unsigned long long v;
        do {
            asm volatile("ld.global.acquire.gpu.u64 %0,[%1];" : "=l"(v) : "l"(&g_barc));
        } while (v < target);
    }
    __syncthreads();
}

// ---------------------------------------------------------------------------
__global__ void __launch_bounds__(NTHR, 2) k_fused(
    const float* __restrict__ x,
    const float* __restrict__ metadata,
    const float* __restrict__ w_ih, const float* __restrict__ b_ih,
    const float* __restrict__ b_hh,
    const float* __restrict__ fc_w,  const float* __restrict__ fc_b,
    const float* __restrict__ fc2_w, const float* __restrict__ fc2_b,
    const float* __restrict__ fc3_w, const float* __restrict__ fc3_b,
    const float* __restrict__ comp_w, const float* __restrict__ comp_b,
    const float* __restrict__ vf_w,  const float* __restrict__ vf_b,
    const float* __restrict__ fcout_w, const float* __restrict__ fcout_b,
    float* __restrict__ out)
{
    __shared__ __align__(16) char shraw[2 * SLICE_LEN * 8 + 64];
    const int tid  = threadIdx.x;
    const int blk  = blockIdx.x;
    const int gtid = blk * NTHR + tid;

    // ============= P1: comp conv partials (blocks 0..255, 16 ch each) ======
    if (blk < 256) {
        const int chunk = blk >> 1;          // 0..127
        const int b     = blk & 1;
        const int c0    = chunk * 16;
        float* sw = (float*)shraw;           // [oc32][cl16] = 512 floats
        for (int idx = tid; idx < 512; idx += NTHR) {
            int oc = idx >> 4, cl = idx & 15;
            sw[idx] = comp_w[oc * 2048 + c0 + cl];
        }
        __syncthreads();

        float acc[32];
#pragma unroll
        for (int oc = 0; oc < 32; ++oc) acc[oc] = 0.f;
        const float* mp = metadata + ((size_t)b * 2048 + c0) * 256 + tid;
#pragma unroll
        for (int cl = 0; cl < 16; ++cl) {
            float mv = __ldg(mp + cl * 256);
#pragma unroll
            for (int oc = 0; oc < 32; ++oc)
                acc[oc] = fmaf(mv, sw[oc * 16 + cl], acc[oc]);
        }
        float4* op = (float4*)(g_comp_part + (size_t)chunk * 16384 + (b * 256 + tid) * 32);
#pragma unroll
        for (int i = 0; i < 8; ++i)
            op[i] = make_float4(acc[4*i], acc[4*i+1], acc[4*i+2], acc[4*i+3]);
        __syncthreads();
    }
    gridbar();

    // ============= P1b: reduce 128 chunk partials ===========================
    if (gtid < 16384) {
        float s = __ldg(comp_b + (gtid & 31));
#pragma unroll 16
        for (int ch = 0; ch < 128; ++ch)
            s += g_comp_part[(size_t)ch * 16384 + gtid];
        g_comp[gtid] = s;
    }
    gridbar();

    // ============= P2: per-token pipeline -> ABC, XR (blocks 0..63) ========
    if (blk < 64) {
        const int m = gtid;
        const int b = m >> 13;
        const int q = m & 8191;
        const int t = q >> 7;

        const float px = __ldg(x + b * 16384 + q);
        const float py = __ldg(x + b * 16384 + 8192 + q);
        const float xr0 = px + sinf((float)t);
        const float xr1 = py + cosf((float)t);

        // single-step LSTM (h0=c0=0), gates i,f,g,o
        float Xl[4];
#pragma unroll
        for (int j = 0; j < 4; ++j) {
            float gi = __ldg(w_ih + 2*j)      * xr0 + __ldg(w_ih + 2*j+1)      * xr1 + __ldg(b_ih + j)      + __ldg(b_hh + j);
            float gg = __ldg(w_ih + 2*(8+j))  * xr0 + __ldg(w_ih + 2*(8+j)+1)  * xr1 + __ldg(b_ih + 8 + j)  + __ldg(b_hh + 8 + j);
            float go = __ldg(w_ih + 2*(12+j)) * xr0 + __ldg(w_ih + 2*(12+j)+1) * xr1 + __ldg(b_ih + 12 + j) + __ldg(b_hh + 12 + j);
            float cst = sigf(gi) * tanhf(gg);
            Xl[j] = sigf(go) * tanhf(cst);
        }

        // bilinear grid-sample of g_comp
        const float ix = px * (1.f / 32.f) - 0.5f;
        const float iy = py * (1.f / 32.f) - 0.5f;
        const float fx0 = floorf(ix), fy0 = floorf(iy);
        const float wx = ix - fx0, wy = iy - fy0;
        const int x0i = (int)fx0, y0i = (int)fy0;

        float lc[32];
#pragma unroll
        for (int c = 0; c < 32; ++c) lc[c] = 0.f;
        const float cw[4] = { (1.f-wy)*(1.f-wx), (1.f-wy)*wx, wy*(1.f-wx), wy*wx };
        const int   cx[4] = { x0i, x0i + 1, x0i,     x0i + 1 };
        const int   cy[4] = { y0i, y0i,     y0i + 1, y0i + 1 };
#pragma unroll
        for (int cn = 0; cn < 4; ++cn) {
            const int xx = cx[cn], yy = cy[cn];
            if (xx >= 0 && xx < 16 && yy >= 0 && yy < 16) {
                const float4* cp = (const float4*)(g_comp + (b * 256 + yy * 16 + xx) * 32);
                const float w = cw[cn];
#pragma unroll
                for (int c4 = 0; c4 < 8; ++c4) {
                    float4 v = cp[c4];
                    lc[4*c4+0] = fmaf(w, v.x, lc[4*c4+0]);
                    lc[4*c4+1] = fmaf(w, v.y, lc[4*c4+1]);
                    lc[4*c4+2] = fmaf(w, v.z, lc[4*c4+2]);
                    lc[4*c4+3] = fmaf(w, v.w, lc[4*c4+3]);
                }
            }
        }

        // vf fusion
        float Xp[4];
#pragma unroll
        for (int j = 0; j < 4; ++j) {
            float s = __ldg(vf_b + j);
#pragma unroll
            for (int k = 0; k < 4; ++k)  s = fmaf(__ldg(vf_w + j*36 + k),     Xl[k], s);
#pragma unroll
            for (int c = 0; c < 32; ++c) s = fmaf(__ldg(vf_w + j*36 + 4 + c), lc[c], s);
            Xp[j] = s;
        }

        // Q, then rank-2 contraction against K's affine map
        float A = 0.f, Bv = 0.f, Cv = 0.f;
#pragma unroll
        for (int d = 0; d < 8; ++d) {
            float qd = __ldg(fc_b + d);
#pragma unroll
            for (int k = 0; k < 4; ++k) qd = fmaf(__ldg(fc_w + d*4 + k), Xp[k], qd);
            A  = fmaf(qd, __ldg(fc2_w + 2*d),     A);
            Bv = fmaf(qd, __ldg(fc2_w + 2*d + 1), Bv);
            Cv = fmaf(qd, __ldg(fc2_b + d),       Cv);
        }
        g_ABC[m] = make_float4(0.5f * A, 0.5f * Bv, 0.5f * Cv, 0.f);
        g_XR[m]  = make_float2(xr0, xr1);

        // block-level Σxr
        float2* sh2 = (float2*)shraw;
        sh2[tid] = make_float2(xr0, xr1);
        __syncthreads();
        for (int off = 128; off > 0; off >>= 1) {
            if (tid < off) {
                sh2[tid].x += sh2[tid + off].x;
                sh2[tid].y += sh2[tid + off].y;
            }
            __syncthreads();
        }
        if (tid == 0) g_xrsum[blk] = sh2[0];
        __syncthreads();
    }
    gridbar();

    // ============= P3: attention — exactly one unit per block ==============
    {
        const int qunit = blk / NSLICE;          // 0..7 (2048 queries each)
        const int ksl   = blk - qunit * NSLICE;  // 0..36
        const int qb    = qunit >> 2;            // batch
        const int k0    = ksl * SLICE_LEN;
        const int klen  = min(SLICE_LEN, TN - k0);

        u64* s_x0 = (u64*)shraw;                 // duplicated xr0
        u64* s_x1 = s_x0 + SLICE_LEN;            // duplicated xr1
        for (int i = tid; i < klen; i += NTHR) {
            float2 v = g_XR[qb * TN + k0 + i];
            s_x0[i] = pack2(v.x, v.x);
            s_x1[i] = pack2(v.y, v.y);
        }
        __syncthreads();

        const int m0 = qunit * 2048 + tid * 8;
        u64 A[4], Bv[4], C[4], S0[4], S1[4], S2[4];
#pragma unroll
        for (int p = 0; p < 4; ++p) {
            float4 a0 = g_ABC[m0 + 2*p];
            float4 a1 = g_ABC[m0 + 2*p + 1];
            A[p]  = pack2(a0.x, a1.x);
            Bv[p] = pack2(a0.y, a1.y);
            C[p]  = pack2(a0.z, a1.z);
            S0[p] = 0ull; S1[p] = 0ull; S2[p] = 0ull;
        }

#pragma unroll 2
        for (int k = 0; k < klen; ++k) {
            const u64 x0 = s_x0[k];
            const u64 x1 = s_x1[k];
#pragma unroll
            for (int p = 0; p < 4; ++p) {
                u64 l = fma2(A[p], x0, fma2(Bv[p], x1, C[p]));
                float l0, l1; unpack2(l, l0, l1);
                const unsigned h = tanh2_f16(l0, l1);       // 1 MUFU, 2 tanhs
                const __half2 th = *reinterpret_cast<const __half2*>(&h);
                const u64 t = pack2(__low2float(th), __high2float(th));
                S0[p] = add2(S0[p], t);
                S1[p] = fma2(t, x0, S1[p]);
                S2[p] = fma2(t, x1, S2[p]);
            }
        }

        float4* op = g_att + (size_t)ksl * M_TOK + m0;
#pragma unroll
        for (int p = 0; p < 4; ++p) {
            float a0, a1, b0, b1, c0, c1;
            unpack2(S0[p], a0, a1); unpack2(S1[p], b0, b1); unpack2(S2[p], c0, c1);
            op[2*p]     = make_float4(a0, b0, c0, 0.f);
            op[2*p + 1] = make_float4(a1, b1, c1, 0.f);
        }
    }
    gridbar();

    // ============= P4: epilogue =============================================
    if (gtid < 16384) {
        const int m = gtid;
        const int b = m >> 13;

        float S0 = 0.f, S1 = 0.f, S2 = 0.f;
#pragma unroll
        for (int ks = 0; ks < NSLICE; ++ks) {
            float4 p = g_att[(size_t)ks * M_TOK + m];
            S0 += p.x; S1 += p.y; S2 += p.z;
        }
        float sx0 = 0.f, sx1 = 0.f;
#pragma unroll
        for (int i = 0; i < 32; ++i) {
            float2 v = g_xrsum[b * 32 + i];
            sx0 += v.x; sx1 += v.y;
        }
        const float f1 = 0.5f * (sx0 + S1);
        const float f2 = 0.5f * (sx1 + S2);
        const float f0 = 0.5f * ((float)TN + S0);

        float r0 = __ldg(fcout_b + 0);
        float r1 = __ldg(fcout_b + 1);
#pragma unroll
        for (int d = 0; d < 8; ++d) {
            float o = f1 * __ldg(fc3_w + 2*d) + f2 * __ldg(fc3_w + 2*d + 1)
                    + f0 * __ldg(fc3_b + d);
            o = (o > 0.5f) ? o : 0.f;
            r0 = fmaf(__ldg(fcout_w + d),     o, r0);
            r1 = fmaf(__ldg(fcout_w + 8 + d), o, r1);
        }
        const int q = m & 8191;
        out[b * 16384 + q]        = r0;
        out[b * 16384 + 8192 + q] = r1;
    }
}

// ---------------------------------------------------------------------------
extern "C" void kernel_launch(void* const* d_in, const int* in_sizes, int n_in,
                              void* d_out, int out_size)
{
    const float* x        = (const float*)d_in[0];
    const float* metadata = (const float*)d_in[1];
    const float* w_ih     = (const float*)d_in[2];
    const float* b_ih     = (const float*)d_in[4];
    const float* b_hh     = (const float*)d_in[5];
    const float* fc_w     = (const float*)d_in[6];
    const float* fc_b     = (const float*)d_in[7];
    const float* fc2_w    = (const float*)d_in[8];
    const float* fc2_b    = (const float*)d_in[9];
    const float* fc3_w    = (const float*)d_in[10];
    const float* fc3_b    = (const float*)d_in[11];
    const float* comp_w   = (const float*)d_in[12];
    const float* comp_b   = (const float*)d_in[13];
    const float* vf_w     = (const float*)d_in[14];
    const float* vf_b     = (const float*)d_in[15];
    const float* fcout_w  = (const float*)d_in[16];
    const float* fcout_b  = (const float*)d_in[17];
    float* out = (float*)d_out;

    k_fused<<<NBLK, NTHR>>>(x, metadata, w_ih, b_ih, b_hh, fc_w, fc_b,
                            fc2_w, fc2_b, fc3_w, fc3_b, comp_w, comp_b,
                            vf_w, vf_b, fcout_w, fcout_b, out);
}

// round 7
// speedup vs baseline: 1.1320x; 1.1320x over previous
#include <cuda_runtime.h>
#include <cuda_fp16.h>
#include <math.h>

// ---------------------------------------------------------------------------
// Persistent kernel, 592 blocks (4/SM), software grid barriers.
// Rank-2 attention: sigmoid(Q·K_k) = 0.5 + 0.5*tanh(A*xr0_k + B*xr1_k + C)
// comp conv + vf projection folded: sample a 4-channel field pf instead of
// the 32-channel comp (bilinear sampling commutes with the linear vf map).
// ---------------------------------------------------------------------------
#define NBLK   592
#define NTHR   256
#define M_TOK  16384
#define TN     8192
#define NSLICE 37          // key slices per batch
#define SLICE_LEN 222      // 37*222 >= 8192

__device__ float4 g_pf_part[128 * 512];        // [chunk][b*256+pix] 4-ch partials
__device__ float  g_pf[2048];                  // [b*256+pix][j]  projected field
__device__ float4 g_ABC[M_TOK];                // (A,B,C,·) per query
__device__ float2 g_XR[M_TOK];                 // xr per token
__device__ float2 g_xrsum[64];                 // per-block Σxr (blocks 0..63)
__device__ float4 g_att[NSLICE * M_TOK];       // (S0,S1,S2,·) partials
__device__ unsigned long long g_barc;          // barrier ticket counter

using u64 = unsigned long long;
__device__ __forceinline__ u64 pack2(float lo, float hi) {
    u64 r; asm("mov.b64 %0,{%1,%2};" : "=l"(r) : "f"(lo), "f"(hi)); return r;
}
__device__ __forceinline__ void unpack2(u64 v, float& lo, float& hi) {
    asm("mov.b64 {%0,%1},%2;" : "=f"(lo), "=f"(hi) : "l"(v));
}
__device__ __forceinline__ u64 fma2(u64 a, u64 b, u64 c) {
    u64 d; asm("fma.rn.f32x2 %0,%1,%2,%3;" : "=l"(d) : "l"(a), "l"(b), "l"(c)); return d;
}
__device__ __forceinline__ u64 add2(u64 a, u64 b) {
    u64 d; asm("add.rn.f32x2 %0,%1,%2;" : "=l"(d) : "l"(a), "l"(b)); return d;
}
// 2 f32 logits -> f16x2 -> ONE MUFU tanh -> 2 f32
__device__ __forceinline__ u64 tanh2(float l0, float l1) {
    unsigned h;
    asm("cvt.rn.f16x2.f32 %0,%1,%2;" : "=r"(h) : "f"(l1), "f"(l0));
    asm("tanh.approx.f16x2 %0,%0;" : "+r"(h));
    const __half2 th = *reinterpret_cast<const __half2*>(&h);
    return pack2(__low2float(th), __high2float(th));
}
__device__ __forceinline__ float sigf(float x) { return 1.f / (1.f + expf(-x)); }

__device__ __forceinline__ void gridbar() {
    __syncthreads();
    if (threadIdx.x == 0) {
        __threadfence();
        unsigned long long ticket = atomicAdd(&g_barc, 1ULL);
        unsigned long long target = (ticket / NBLK + 1ULL) * (unsigned long long)NBLK;
        unsigned long long v;
        do {
            asm volatile("ld.global.acquire.gpu.u64 %0,[%1];" : "=l"(v) : "l"(&g_barc));
        } while (v < target);
    }
    __syncthreads();
}

// ---------------------------------------------------------------------------
__global__ void __launch_bounds__(NTHR, 4) k_fused(
    const float* __restrict__ x,
    const float* __restrict__ metadata,
    const float* __restrict__ w_ih, const float* __restrict__ b_ih,
    const float* __restrict__ b_hh,
    const float* __restrict__ fc_w,  const float* __restrict__ fc_b,
    const float* __restrict__ fc2_w, const float* __restrict__ fc2_b,
    const float* __restrict__ fc3_w, const float* __restrict__ fc3_b,
    const float* __restrict__ comp_w, const float* __restrict__ comp_b,
    const float* __restrict__ vf_w,  const float* __restrict__ vf_b,
    const float* __restrict__ fcout_w, const float* __restrict__ fcout_b,
    float* __restrict__ out)
{
    __shared__ __align__(16) char shraw[2 * SLICE_LEN * 8 + 64];
    const int tid  = threadIdx.x;
    const int blk  = blockIdx.x;
    const int gtid = blk * NTHR + tid;

    // ===== P1: projected conv partials (blocks 0..255, 16 in-ch each) ======
    // pf_part[chunk][b][pix][j] = Σ_{C in chunk} metadata[b][C][pix] * W'[j][C]
    // where W'[j][C] = Σ_c vf_w[j][4+c] * comp_w[c][C]  (computed per block)
    if (blk < 256) {
        const int chunk = blk >> 1;          // 0..127
        const int b     = blk & 1;
        const int c0    = chunk * 16;
        float* sWp = (float*)shraw;          // [j4][cl16]
        if (tid < 64) {
            const int j = tid >> 4, cl = tid & 15;
            const float* vw = vf_w + j * 36 + 4;
            float s = 0.f;
#pragma unroll
            for (int c = 0; c < 32; ++c)
                s = fmaf(__ldg(vw + c), __ldg(comp_w + c * 2048 + c0 + cl), s);
            sWp[tid] = s;
        }
        __syncthreads();

        float a0 = 0.f, a1 = 0.f, a2 = 0.f, a3 = 0.f;
        const float* mp = metadata + ((size_t)b * 2048 + c0) * 256 + tid;
#pragma unroll
        for (int cl = 0; cl < 16; ++cl) {
            const float mv = __ldg(mp + cl * 256);
            a0 = fmaf(mv, sWp[cl],      a0);
            a1 = fmaf(mv, sWp[16 + cl], a1);
            a2 = fmaf(mv, sWp[32 + cl], a2);
            a3 = fmaf(mv, sWp[48 + cl], a3);
        }
        g_pf_part[chunk * 512 + b * 256 + tid] = make_float4(a0, a1, a2, a3);
        __syncthreads();
    }
    gridbar();

    // ===== P1b: reduce 128 chunk partials + bias' ===========================
    if (gtid < 2048) {
        const int idx = gtid >> 2;           // (b*256+pix)
        const int j   = gtid & 3;
        float s = 0.f;
#pragma unroll
        for (int c = 0; c < 32; ++c)         // b'[j] = Σ_c comp_b[c]*vf_w[j][4+c]
            s = fmaf(__ldg(vf_w + j * 36 + 4 + c), __ldg(comp_b + c), s);
        const float* pp = (const float*)g_pf_part + idx * 4 + j;
#pragma unroll 8
        for (int ch = 0; ch < 128; ++ch)
            s += pp[(size_t)ch * 2048];
        g_pf[idx * 4 + j] = s;
    }
    gridbar();

    // ===== P2: per-token pipeline -> ABC, XR (blocks 0..63) =================
    if (blk < 64) {
        const int m = gtid;
        const int b = m >> 13;
        const int q = m & 8191;
        const int t = q >> 7;

        const float px = __ldg(x + b * 16384 + q);
        const float py = __ldg(x + b * 16384 + 8192 + q);
        const float xr0 = px + sinf((float)t);
        const float xr1 = py + cosf((float)t);

        // single-step LSTM (h0=c0=0), gates i,f,g,o
        float Xl[4];
#pragma unroll
        for (int j = 0; j < 4; ++j) {
            float gi = __ldg(w_ih + 2*j)      * xr0 + __ldg(w_ih + 2*j+1)      * xr1 + __ldg(b_ih + j)      + __ldg(b_hh + j);
            float gg = __ldg(w_ih + 2*(8+j))  * xr0 + __ldg(w_ih + 2*(8+j)+1)  * xr1 + __ldg(b_ih + 8 + j)  + __ldg(b_hh + 8 + j);
            float go = __ldg(w_ih + 2*(12+j)) * xr0 + __ldg(w_ih + 2*(12+j)+1) * xr1 + __ldg(b_ih + 12 + j) + __ldg(b_hh + 12 + j);
            float cst = sigf(gi) * tanhf(gg);
            Xl[j] = sigf(go) * tanhf(cst);
        }

        // bilinear grid-sample of the PROJECTED 4-channel field
        const float ix = px * (1.f / 32.f) - 0.5f;
        const float iy = py * (1.f / 32.f) - 0.5f;
        const float fx0 = floorf(ix), fy0 = floorf(iy);
        const float wx = ix - fx0, wy = iy - fy0;
        const int x0i = (int)fx0, y0i = (int)fy0;

        float lp0 = 0.f, lp1 = 0.f, lp2 = 0.f, lp3 = 0.f;
        const float cw[4] = { (1.f-wy)*(1.f-wx), (1.f-wy)*wx, wy*(1.f-wx), wy*wx };
        const int   cx[4] = { x0i, x0i + 1, x0i,     x0i + 1 };
        const int   cy[4] = { y0i, y0i,     y0i + 1, y0i + 1 };
        const float4* pf = (const float4*)g_pf;
#pragma unroll
        for (int cn = 0; cn < 4; ++cn) {
            const int xx = cx[cn], yy = cy[cn];
            if (xx >= 0 && xx < 16 && yy >= 0 && yy < 16) {
                const float4 v = pf[b * 256 + yy * 16 + xx];
                const float w = cw[cn];
                lp0 = fmaf(w, v.x, lp0);
                lp1 = fmaf(w, v.y, lp1);
                lp2 = fmaf(w, v.z, lp2);
                lp3 = fmaf(w, v.w, lp3);
            }
        }

        // vf fusion (lc contribution already projected)
        float Xp[4] = { lp0, lp1, lp2, lp3 };
#pragma unroll
        for (int j = 0; j < 4; ++j) {
            float s = Xp[j] + __ldg(vf_b + j);
#pragma unroll
            for (int k = 0; k < 4; ++k)
                s = fmaf(__ldg(vf_w + j*36 + k), Xl[k], s);
            Xp[j] = s;
        }

        // Q, then rank-2 contraction against K's affine map
        float A = 0.f, Bv = 0.f, Cv = 0.f;
#pragma unroll
        for (int d = 0; d < 8; ++d) {
            float qd = __ldg(fc_b + d);
#pragma unroll
            for (int k = 0; k < 4; ++k) qd = fmaf(__ldg(fc_w + d*4 + k), Xp[k], qd);
            A  = fmaf(qd, __ldg(fc2_w + 2*d),     A);
            Bv = fmaf(qd, __ldg(fc2_w + 2*d + 1), Bv);
            Cv = fmaf(qd, __ldg(fc2_b + d),       Cv);
        }
        g_ABC[m] = make_float4(0.5f * A, 0.5f * Bv, 0.5f * Cv, 0.f);
        g_XR[m]  = make_float2(xr0, xr1);

        // block-level Σxr
        float2* sh2 = (float2*)shraw;
        sh2[tid] = make_float2(xr0, xr1);
        __syncthreads();
        for (int off = 128; off > 0; off >>= 1) {
            if (tid < off) {
                sh2[tid].x += sh2[tid + off].x;
                sh2[tid].y += sh2[tid + off].y;
            }
            __syncthreads();
        }
        if (tid == 0) g_xrsum[blk] = sh2[0];
        __syncthreads();
    }
    gridbar();

    // ===== P3: attention — exactly one unit per block (16 qunits x 37) =====
    {
        const int qunit = blk / NSLICE;          // 0..15 (1024 queries each)
        const int ksl   = blk - qunit * NSLICE;  // 0..36
        const int qb    = qunit >> 3;            // batch
        const int k0    = ksl * SLICE_LEN;
        const int klen  = min(SLICE_LEN, TN - k0);

        u64* s_x0 = (u64*)shraw;                 // duplicated xr0
        u64* s_x1 = s_x0 + SLICE_LEN;            // duplicated xr1
        for (int i = tid; i < klen; i += NTHR) {
            float2 v = g_XR[qb * TN + k0 + i];
            s_x0[i] = pack2(v.x, v.x);
            s_x1[i] = pack2(v.y, v.y);
        }
        __syncthreads();

        const int m0 = qunit * 1024 + tid * 4;   // 4 queries = 2 u64 slots
        u64 A[2], Bv[2], C[2], S0[2], S1[2], S2[2];
#pragma unroll
        for (int p = 0; p < 2; ++p) {
            float4 a0 = g_ABC[m0 + 2*p];
            float4 a1 = g_ABC[m0 + 2*p + 1];
            A[p]  = pack2(a0.x, a1.x);
            Bv[p] = pack2(a0.y, a1.y);
            C[p]  = pack2(a0.z, a1.z);
            S0[p] = 0ull; S1[p] = 0ull; S2[p] = 0ull;
        }

#pragma unroll 4
        for (int k = 0; k < klen; ++k) {
            const u64 x0 = s_x0[k];
            const u64 x1 = s_x1[k];
#pragma unroll
            for (int p = 0; p < 2; ++p) {
                u64 l = fma2(A[p], x0, fma2(Bv[p], x1, C[p]));
                float l0, l1; unpack2(l, l0, l1);
                const u64 t = tanh2(l0, l1);     // 1 MUFU, 2 tanhs
                S0[p] = add2(S0[p], t);
                S1[p] = fma2(t, x0, S1[p]);
                S2[p] = fma2(t, x1, S2[p]);
            }
        }

        float4* op = g_att + (size_t)ksl * M_TOK + m0;
#pragma unroll
        for (int p = 0; p < 2; ++p) {
            float a0, a1, b0, b1, c0, c1;
            unpack2(S0[p], a0, a1); unpack2(S1[p], b0, b1); unpack2(S2[p], c0, c1);
            op[2*p]     = make_float4(a0, b0, c0, 0.f);
            op[2*p + 1] = make_float4(a1, b1, c1, 0.f);
        }
    }
    gridbar();

    // ===== P4: epilogue ======================================================
    if (gtid < 16384) {
        const int m = gtid;
        const int b = m >> 13;

        float S0 = 0.f, S1 = 0.f, S2 = 0.f;
#pragma unroll
        for (int ks = 0; ks < NSLICE; ++ks) {
            float4 p = g_att[(size_t)ks * M_TOK + m];
            S0 += p.x; S1 += p.y; S2 += p.z;
        }
        float sx0 = 0.f, sx1 = 0.f;
#pragma unroll
        for (int i = 0; i < 32; ++i) {
            float2 v = g_xrsum[b * 32 + i];
            sx0 += v.x; sx1 += v.y;
        }
        const float f1 = 0.5f * (sx0 + S1);
        const float f2 = 0.5f * (sx1 + S2);
        const float f0 = 0.5f * ((float)TN + S0);

        float r0 = __ldg(fcout_b + 0);
        float r1 = __ldg(fcout_b + 1);
#pragma unroll
        for (int d = 0; d < 8; ++d) {
            float o = f1 * __ldg(fc3_w + 2*d) + f2 * __ldg(fc3_w + 2*d + 1)
                    + f0 * __ldg(fc3_b + d);
            o = (o > 0.5f) ? o : 0.f;
            r0 = fmaf(__ldg(fcout_w + d),     o, r0);
            r1 = fmaf(__ldg(fcout_w + 8 + d), o, r1);
        }
        const int q = m & 8191;
        out[b * 16384 + q]        = r0;
        out[b * 16384 + 8192 + q] = r1;
    }
}

// ---------------------------------------------------------------------------
extern "C" void kernel_launch(void* const* d_in, const int* in_sizes, int n_in,
                              void* d_out, int out_size)
{
    const float* x        = (const float*)d_in[0];
    const float* metadata = (const float*)d_in[1];
    const float* w_ih     = (const float*)d_in[2];
    const float* b_ih     = (const float*)d_in[4];
    const float* b_hh     = (const float*)d_in[5];
    const float* fc_w     = (const float*)d_in[6];
    const float* fc_b     = (const float*)d_in[7];
    const float* fc2_w    = (const float*)d_in[8];
    const float* fc2_b    = (const float*)d_in[9];
    const float* fc3_w    = (const float*)d_in[10];
    const float* fc3_b    = (const float*)d_in[11];
    const float* comp_w   = (const float*)d_in[12];
    const float* comp_b   = (const float*)d_in[13];
    const float* vf_w     = (const float*)d_in[14];
    const float* vf_b     = (const float*)d_in[15];
    const float* fcout_w  = (const float*)d_in[16];
    const float* fcout_b  = (const float*)d_in[17];
    float* out = (float*)d_out;

    k_fused<<<NBLK, NTHR>>>(x, metadata, w_ih, b_ih, b_hh, fc_w, fc_b,
                            fc2_w, fc2_b, fc3_w, fc3_b, comp_w, comp_b,
                            vf_w, vf_b, fcout_w, fcout_b, out);
}

// round 8
// speedup vs baseline: 1.2274x; 1.0842x over previous
#include <cuda_runtime.h>
#include <cuda_fp16.h>
#include <math.h>

// ---------------------------------------------------------------------------
// Persistent kernel, 592 blocks (4/SM), 4 software grid barriers.
// A: conv partials (blk 0..63) || token pre-pass xr/Xl (blk 64..127)
// B: warp-shuffle reduce partials -> g_pf (blk 0..255)
// C: sample pf + ABC (blk 0..63)
// D: rank-2 attention, f16x2 tanh (all 592, one unit each)
// E: epilogue (blk 0..63)
// ---------------------------------------------------------------------------
#define NBLK   592
#define NTHR   256
#define M_TOK  16384
#define TN     8192
#define NSLICE 37
#define SLICE_LEN 222      // 37*222 >= 8192

__device__ float  g_pf_part[2048 * 32];        // [out][chunk] transposed
__device__ float  g_pf[2048];                  // [b*256+pix][j]
__device__ float4 g_Xl[M_TOK];                 // LSTM output per token
__device__ float4 g_ABC[M_TOK];                // (A,B,C,·) per query
__device__ float2 g_XR[M_TOK];                 // xr per token
__device__ float2 g_xrsum[64];                 // per-block Σxr
__device__ float4 g_att[NSLICE * M_TOK];       // (S0,S1,S2,·) partials
__device__ unsigned long long g_barc;

using u64 = unsigned long long;
__device__ __forceinline__ u64 pack2(float lo, float hi) {
    u64 r; asm("mov.b64 %0,{%1,%2};" : "=l"(r) : "f"(lo), "f"(hi)); return r;
}
__device__ __forceinline__ void unpack2(u64 v, float& lo, float& hi) {
    asm("mov.b64 {%0,%1},%2;" : "=f"(lo), "=f"(hi) : "l"(v));
}
__device__ __forceinline__ u64 fma2(u64 a, u64 b, u64 c) {
    u64 d; asm("fma.rn.f32x2 %0,%1,%2,%3;" : "=l"(d) : "l"(a), "l"(b), "l"(c)); return d;
}
__device__ __forceinline__ u64 add2(u64 a, u64 b) {
    u64 d; asm("add.rn.f32x2 %0,%1,%2;" : "=l"(d) : "l"(a), "l"(b)); return d;
}
__device__ __forceinline__ u64 tanh2(float l0, float l1) {   // 1 MUFU, 2 tanhs
    unsigned h;
    asm("cvt.rn.f16x2.f32 %0,%1,%2;" : "=r"(h) : "f"(l1), "f"(l0));
    asm("tanh.approx.f16x2 %0,%0;" : "+r"(h));
    const __half2 th = *reinterpret_cast<const __half2*>(&h);
    return pack2(__low2float(th), __high2float(th));
}
__device__ __forceinline__ float tanha(float x) {
    float r; asm("tanh.approx.f32 %0,%1;" : "=f"(r) : "f"(x)); return r;
}
__device__ __forceinline__ float sigf(float x) {             // fast sigmoid
    return __fdividef(1.f, 1.f + __expf(-x));
}

__device__ __forceinline__ void gridbar() {
    __syncthreads();
    if (threadIdx.x == 0) {
        __threadfence();
        unsigned long long ticket = atomicAdd(&g_barc, 1ULL);
        unsigned long long target = (ticket / NBLK + 1ULL) * (unsigned long long)NBLK;
        unsigned long long v;
        do {
            asm volatile("ld.global.acquire.gpu.u64 %0,[%1];" : "=l"(v) : "l"(&g_barc));
        } while (v < target);
    }
    __syncthreads();
}

// ---------------------------------------------------------------------------
__global__ void __launch_bounds__(NTHR, 4) k_fused(
    const float* __restrict__ x,
    const float* __restrict__ metadata,
    const float* __restrict__ w_ih, const float* __restrict__ b_ih,
    const float* __restrict__ b_hh,
    const float* __restrict__ fc_w,  const float* __restrict__ fc_b,
    const float* __restrict__ fc2_w, const float* __restrict__ fc2_b,
    const float* __restrict__ fc3_w, const float* __restrict__ fc3_b,
    const float* __restrict__ comp_w, const float* __restrict__ comp_b,
    const float* __restrict__ vf_w,  const float* __restrict__ vf_b,
    const float* __restrict__ fcout_w, const float* __restrict__ fcout_b,
    float* __restrict__ out)
{
    __shared__ __align__(16) char shraw[2 * SLICE_LEN * 8 + 64];
    const int tid  = threadIdx.x;
    const int blk  = blockIdx.x;
    const int gtid = blk * NTHR + tid;

    // ===== Phase A ==========================================================
    if (blk < 64) {
        // --- conv partials: chunk = blk>>1 (64 in-ch), b = blk&1 ---
        const int chunk = blk >> 1;
        const int b     = blk & 1;
        const int c0    = chunk * 64;
        float* sWp = (float*)shraw;          // [j4][cl64]
        {
            const int j = tid >> 6, cl = tid & 63;   // all 256 threads
            const float* vw = vf_w + j * 36 + 4;
            float s = 0.f;
#pragma unroll
            for (int c = 0; c < 32; ++c)
                s = fmaf(__ldg(vw + c), __ldg(comp_w + c * 2048 + c0 + cl), s);
            sWp[tid] = s;
        }
        __syncthreads();

        float a0 = 0.f, a1 = 0.f, a2 = 0.f, a3 = 0.f;
        const float* mp = metadata + ((size_t)b * 2048 + c0) * 256 + tid;
#pragma unroll 8
        for (int cl = 0; cl < 64; ++cl) {
            const float mv = __ldg(mp + cl * 256);
            a0 = fmaf(mv, sWp[cl],       a0);
            a1 = fmaf(mv, sWp[64 + cl],  a1);
            a2 = fmaf(mv, sWp[128 + cl], a2);
            a3 = fmaf(mv, sWp[192 + cl], a3);
        }
        const int o = (b * 256 + tid) * 4;   // 4 outputs, transposed [o][chunk]
        g_pf_part[(o + 0) * 32 + chunk] = a0;
        g_pf_part[(o + 1) * 32 + chunk] = a1;
        g_pf_part[(o + 2) * 32 + chunk] = a2;
        g_pf_part[(o + 3) * 32 + chunk] = a3;
        __syncthreads();
    } else if (blk < 128) {
        // --- token pre-pass: xr + LSTM ---
        const int m = (blk - 64) * NTHR + tid;
        const int b = m >> 13;
        const int q = m & 8191;
        const int t = q >> 7;

        const float px = __ldg(x + b * 16384 + q);
        const float py = __ldg(x + b * 16384 + 8192 + q);
        const float xr0 = px + __sinf((float)t);
        const float xr1 = py + __cosf((float)t);

        float Xl[4];
#pragma unroll
        for (int j = 0; j < 4; ++j) {
            float gi = __ldg(w_ih + 2*j)      * xr0 + __ldg(w_ih + 2*j+1)      * xr1 + __ldg(b_ih + j)      + __ldg(b_hh + j);
            float gg = __ldg(w_ih + 2*(8+j))  * xr0 + __ldg(w_ih + 2*(8+j)+1)  * xr1 + __ldg(b_ih + 8 + j)  + __ldg(b_hh + 8 + j);
            float go = __ldg(w_ih + 2*(12+j)) * xr0 + __ldg(w_ih + 2*(12+j)+1) * xr1 + __ldg(b_ih + 12 + j) + __ldg(b_hh + 12 + j);
            float cst = sigf(gi) * tanha(gg);
            Xl[j] = sigf(go) * tanha(cst);
        }
        g_Xl[m] = make_float4(Xl[0], Xl[1], Xl[2], Xl[3]);
        g_XR[m] = make_float2(xr0, xr1);

        float2* sh2 = (float2*)shraw;
        sh2[tid] = make_float2(xr0, xr1);
        __syncthreads();
        for (int off = 128; off > 0; off >>= 1) {
            if (tid < off) {
                sh2[tid].x += sh2[tid + off].x;
                sh2[tid].y += sh2[tid + off].y;
            }
            __syncthreads();
        }
        if (tid == 0) g_xrsum[blk - 64] = sh2[0];
        __syncthreads();
    }
    gridbar();

    // ===== Phase B: reduce partials (blocks 0..255, 8 outputs each) ========
    if (blk < 256) {
        const int o    = blk * 8 + (tid >> 5);
        const int lane = tid & 31;                 // = chunk
        const int j    = o & 3;
        float v = g_pf_part[o * 32 + lane]
                + __ldg(vf_w + j * 36 + 4 + lane) * __ldg(comp_b + lane);
#pragma unroll
        for (int off = 16; off > 0; off >>= 1)
            v += __shfl_down_sync(0xffffffffu, v, off);
        if (lane == 0) g_pf[o] = v;
    }
    gridbar();

    // ===== Phase C: sample pf + ABC (blocks 0..63) ==========================
    if (blk < 64) {
        const int m = gtid;
        const int b = m >> 13;
        const int q = m & 8191;

        const float px = __ldg(x + b * 16384 + q);
        const float py = __ldg(x + b * 16384 + 8192 + q);
        const float2 xr = g_XR[m];
        const float4 Xlv = g_Xl[m];
        const float Xl[4] = { Xlv.x, Xlv.y, Xlv.z, Xlv.w };

        const float ix = px * (1.f / 32.f) - 0.5f;
        const float iy = py * (1.f / 32.f) - 0.5f;
        const float fx0 = floorf(ix), fy0 = floorf(iy);
        const float wx = ix - fx0, wy = iy - fy0;
        const int x0i = (int)fx0, y0i = (int)fy0;

        float lp0 = 0.f, lp1 = 0.f, lp2 = 0.f, lp3 = 0.f;
        const float cw[4] = { (1.f-wy)*(1.f-wx), (1.f-wy)*wx, wy*(1.f-wx), wy*wx };
        const int   cx[4] = { x0i, x0i + 1, x0i,     x0i + 1 };
        const int   cy[4] = { y0i, y0i,     y0i + 1, y0i + 1 };
        const float4* pf = (const float4*)g_pf;
#pragma unroll
        for (int cn = 0; cn < 4; ++cn) {
            const int xx = cx[cn], yy = cy[cn];
            if (xx >= 0 && xx < 16 && yy >= 0 && yy < 16) {
                const float4 v = pf[b * 256 + yy * 16 + xx];
                const float w = cw[cn];
                lp0 = fmaf(w, v.x, lp0);
                lp1 = fmaf(w, v.y, lp1);
                lp2 = fmaf(w, v.z, lp2);
                lp3 = fmaf(w, v.w, lp3);
            }
        }

        float Xp[4] = { lp0, lp1, lp2, lp3 };
#pragma unroll
        for (int j = 0; j < 4; ++j) {
            float s = Xp[j] + __ldg(vf_b + j);
#pragma unroll
            for (int k = 0; k < 4; ++k)
                s = fmaf(__ldg(vf_w + j*36 + k), Xl[k], s);
            Xp[j] = s;
        }

        float A = 0.f, Bv = 0.f, Cv = 0.f;
#pragma unroll
        for (int d = 0; d < 8; ++d) {
            float qd = __ldg(fc_b + d);
#pragma unroll
            for (int k = 0; k < 4; ++k) qd = fmaf(__ldg(fc_w + d*4 + k), Xp[k], qd);
            A  = fmaf(qd, __ldg(fc2_w + 2*d),     A);
            Bv = fmaf(qd, __ldg(fc2_w + 2*d + 1), Bv);
            Cv = fmaf(qd, __ldg(fc2_b + d),       Cv);
        }
        g_ABC[m] = make_float4(0.5f * A, 0.5f * Bv, 0.5f * Cv, 0.f);
    }
    gridbar();

    // ===== Phase D: attention — one unit per block (16 qunits x 37) ========
    {
        const int qunit = blk / NSLICE;          // 0..15 (1024 queries each)
        const int ksl   = blk - qunit * NSLICE;  // 0..36
        const int qb    = qunit >> 3;
        const int k0    = ksl * SLICE_LEN;
        const int klen  = min(SLICE_LEN, TN - k0);

        u64* s_x0 = (u64*)shraw;
        u64* s_x1 = s_x0 + SLICE_LEN;
        for (int i = tid; i < klen; i += NTHR) {
            float2 v = g_XR[qb * TN + k0 + i];
            s_x0[i] = pack2(v.x, v.x);
            s_x1[i] = pack2(v.y, v.y);
        }
        __syncthreads();

        const int m0 = qunit * 1024 + tid * 4;
        u64 A[2], Bv[2], C[2], S0[2], S1[2], S2[2];
#pragma unroll
        for (int p = 0; p < 2; ++p) {
            float4 a0 = g_ABC[m0 + 2*p];
            float4 a1 = g_ABC[m0 + 2*p + 1];
            A[p]  = pack2(a0.x, a1.x);
            Bv[p] = pack2(a0.y, a1.y);
            C[p]  = pack2(a0.z, a1.z);
            S0[p] = 0ull; S1[p] = 0ull; S2[p] = 0ull;
        }

#pragma unroll 4
        for (int k = 0; k < klen; ++k) {
            const u64 x0 = s_x0[k];
            const u64 x1 = s_x1[k];
#pragma unroll
            for (int p = 0; p < 2; ++p) {
                u64 l = fma2(A[p], x0, fma2(Bv[p], x1, C[p]));
                float l0, l1; unpack2(l, l0, l1);
                const u64 t = tanh2(l0, l1);
                S0[p] = add2(S0[p], t);
                S1[p] = fma2(t, x0, S1[p]);
                S2[p] = fma2(t, x1, S2[p]);
            }
        }

        float4* op = g_att + (size_t)ksl * M_TOK + m0;
#pragma unroll
        for (int p = 0; p < 2; ++p) {
            float a0, a1, b0, b1, c0, c1;
            unpack2(S0[p], a0, a1); unpack2(S1[p], b0, b1); unpack2(S2[p], c0, c1);
            op[2*p]     = make_float4(a0, b0, c0, 0.f);
            op[2*p + 1] = make_float4(a1, b1, c1, 0.f);
        }
    }
    gridbar();

    // ===== Phase E: epilogue (blocks 0..63) =================================
    if (blk < 64) {
        const int m = gtid;
        const int b = m >> 13;

        float S0 = 0.f, S1 = 0.f, S2 = 0.f;
#pragma unroll
        for (int ks = 0; ks < NSLICE; ++ks) {
            float4 p = g_att[(size_t)ks * M_TOK + m];
            S0 += p.x; S1 += p.y; S2 += p.z;
        }
        float sx0 = 0.f, sx1 = 0.f;
#pragma unroll
        for (int i = 0; i < 32; ++i) {
            float2 v = g_xrsum[b * 32 + i];
            sx0 += v.x; sx1 += v.y;
        }
        const float f1 = 0.5f * (sx0 + S1);
        const float f2 = 0.5f * (sx1 + S2);
        const float f0 = 0.5f * ((float)TN + S0);

        float r0 = __ldg(fcout_b + 0);
        float r1 = __ldg(fcout_b + 1);
#pragma unroll
        for (int d = 0; d < 8; ++d) {
            float o = f1 * __ldg(fc3_w + 2*d) + f2 * __ldg(fc3_w + 2*d + 1)
                    + f0 * __ldg(fc3_b + d);
            o = (o > 0.5f) ? o : 0.f;
            r0 = fmaf(__ldg(fcout_w + d),     o, r0);
            r1 = fmaf(__ldg(fcout_w + 8 + d), o, r1);
        }
        const int q = m & 8191;
        out[b * 16384 + q]        = r0;
        out[b * 16384 + 8192 + q] = r1;
    }
}

// ---------------------------------------------------------------------------
extern "C" void kernel_launch(void* const* d_in, const int* in_sizes, int n_in,
                              void* d_out, int out_size)
{
    const float* x        = (const float*)d_in[0];
    const float* metadata = (const float*)d_in[1];
    const float* w_ih     = (const float*)d_in[2];
    const float* b_ih     = (const float*)d_in[4];
    const float* b_hh     = (const float*)d_in[5];
    const float* fc_w     = (const float*)d_in[6];
    const float* fc_b     = (const float*)d_in[7];
    const float* fc2_w    = (const float*)d_in[8];
    const float* fc2_b    = (const float*)d_in[9];
    const float* fc3_w    = (const float*)d_in[10];
    const float* fc3_b    = (const float*)d_in[11];
    const float* comp_w   = (const float*)d_in[12];
    const float* comp_b   = (const float*)d_in[13];
    const float* vf_w     = (const float*)d_in[14];
    const float* vf_b     = (const float*)d_in[15];
    const float* fcout_w  = (const float*)d_in[16];
    const float* fcout_b  = (const float*)d_in[17];
    float* out = (float*)d_out;

    k_fused<<<NBLK, NTHR>>>(x, metadata, w_ih, b_ih, b_hh, fc_w, fc_b,
                            fc2_w, fc2_b, fc3_w, fc3_b, comp_w, comp_b,
                            vf_w, vf_b, fcout_w, fcout_b, out);
}